// round 1
// baseline (speedup 1.0000x reference)
#include <cuda_runtime.h>
#include <math.h>

// Problem constants
#define BATCH 4
#define TLEN  4096
#define EDIM  1024
#define DDIM  128
#define MTOT  (BATCH*TLEN)          // 16384
#define ATTN_SCALE 0.08838834764831843f  // 1/sqrt(128)

// Scratch (device globals — no allocation allowed)
__device__ float g_q[MTOT*DDIM];
__device__ float g_k[MTOT*DDIM];
__device__ float g_v[MTOT*DDIM];
__device__ float g_o[MTOT*DDIM];

// ---------------------------------------------------------------------------
// C[M,128] = A[M,K] @ B[K,128], row-major. BM=64 per CTA, 256 threads,
// 4x8 register microtile per thread, BK=32.
// ---------------------------------------------------------------------------
__global__ __launch_bounds__(256) void gemm_n128(
    const float* __restrict__ A, const float* __restrict__ B,
    float* __restrict__ C, int K)
{
    __shared__ float As[32][68];    // transposed: As[k][m], pad 4
    __shared__ float Bs[32][132];   // Bs[k][n], pad 4

    const int m0  = blockIdx.x * 64;
    const int t   = threadIdx.x;
    const int rbi = t >> 4;         // 0..15 -> rows rbi*4..+3
    const int cbi = t & 15;         // 0..15 -> cols cbi*8..+7

    float acc[4][8];
#pragma unroll
    for (int i = 0; i < 4; i++)
#pragma unroll
        for (int j = 0; j < 8; j++) acc[i][j] = 0.f;

    for (int k0 = 0; k0 < K; k0 += 32) {
        // A tile 64x32, float4 along k, store transposed
        for (int i = t * 4; i < 64 * 32; i += 1024) {
            int r = i >> 5, c = i & 31;
            float4 v = *(const float4*)(A + (size_t)(m0 + r) * K + k0 + c);
            As[c + 0][r] = v.x; As[c + 1][r] = v.y;
            As[c + 2][r] = v.z; As[c + 3][r] = v.w;
        }
        // B tile 32x128
        for (int i = t * 4; i < 32 * 128; i += 1024) {
            int r = i >> 7, c = i & 127;
            *(float4*)&Bs[r][c] = *(const float4*)(B + (size_t)(k0 + r) * 128 + c);
        }
        __syncthreads();

#pragma unroll 8
        for (int kk = 0; kk < 32; kk++) {
            float4 a4 = *(float4*)&As[kk][rbi * 4];
            float4 b0 = *(float4*)&Bs[kk][cbi * 8];
            float4 b1 = *(float4*)&Bs[kk][cbi * 8 + 4];
            float a[4]  = {a4.x, a4.y, a4.z, a4.w};
            float bb[8] = {b0.x, b0.y, b0.z, b0.w, b1.x, b1.y, b1.z, b1.w};
#pragma unroll
            for (int i = 0; i < 4; i++)
#pragma unroll
                for (int j = 0; j < 8; j++)
                    acc[i][j] = fmaf(a[i], bb[j], acc[i][j]);
        }
        __syncthreads();
    }

#pragma unroll
    for (int i = 0; i < 4; i++) {
        size_t r = (size_t)(m0 + rbi * 4 + i);
        *(float4*)(C + r * 128 + cbi * 8) =
            make_float4(acc[i][0], acc[i][1], acc[i][2], acc[i][3]);
        *(float4*)(C + r * 128 + cbi * 8 + 4) =
            make_float4(acc[i][4], acc[i][5], acc[i][6], acc[i][7]);
    }
}

// ---------------------------------------------------------------------------
// Causal flash attention, fp32. BM=BN=64, D=128. One CTA per (batch, q-tile).
// Dynamic smem: Q(64x132) K(64x132) V(64x132) S(64x68) + m/l/scale(64 each)
// ---------------------------------------------------------------------------
__global__ __launch_bounds__(256) void flash_attn(
    const float* __restrict__ gq, const float* __restrict__ gk,
    const float* __restrict__ gv, float* __restrict__ go)
{
    extern __shared__ float sm[];
    float* Qs  = sm;                 // 64*132
    float* Ks  = Qs + 64 * 132;
    float* Vs  = Ks + 64 * 132;
    float* Ss  = Vs + 64 * 132;      // 64*68
    float* m_s = Ss + 64 * 68;
    float* l_s = m_s + 64;
    float* c_s = l_s + 64;

    const int b  = blockIdx.y;
    const int mt = gridDim.x - 1 - blockIdx.x;  // heavy tiles first
    const int m0 = mt * 64;
    const int t  = threadIdx.x;

    const float* Qb = gq + (size_t)b * TLEN * DDIM;
    const float* Kb = gk + (size_t)b * TLEN * DDIM;
    const float* Vb = gv + (size_t)b * TLEN * DDIM;

    for (int i = t * 4; i < 64 * 128; i += 1024) {
        int r = i >> 7, c = i & 127;
        *(float4*)&Qs[r * 132 + c] =
            *(const float4*)(Qb + (size_t)(m0 + r) * 128 + c);
    }
    if (t < 64) { m_s[t] = -INFINITY; l_s[t] = 0.f; }

    const int rbi = t >> 4, cbi = t & 15;
    const int r0  = rbi * 4;

    float acc[4][8];
#pragma unroll
    for (int i = 0; i < 4; i++)
#pragma unroll
        for (int j = 0; j < 8; j++) acc[i][j] = 0.f;

    __syncthreads();

    for (int nt = 0; nt <= mt; nt++) {
        const int n0 = nt * 64;

        // Load K,V tiles
        for (int i = t * 4; i < 64 * 128; i += 1024) {
            int r = i >> 7, c = i & 127;
            *(float4*)&Ks[r * 132 + c] =
                *(const float4*)(Kb + (size_t)(n0 + r) * 128 + c);
            *(float4*)&Vs[r * 132 + c] =
                *(const float4*)(Vb + (size_t)(n0 + r) * 128 + c);
        }
        __syncthreads();

        // S = Q K^T : thread computes 4x4 tile
        float s[4][4];
#pragma unroll
        for (int i = 0; i < 4; i++)
#pragma unroll
            for (int j = 0; j < 4; j++) s[i][j] = 0.f;

#pragma unroll 4
        for (int kk = 0; kk < 128; kk += 4) {
            float4 qa[4], kb4[4];
#pragma unroll
            for (int i = 0; i < 4; i++)
                qa[i] = *(float4*)&Qs[(r0 + i) * 132 + kk];
#pragma unroll
            for (int j = 0; j < 4; j++)
                kb4[j] = *(float4*)&Ks[(cbi * 4 + j) * 132 + kk];
#pragma unroll
            for (int i = 0; i < 4; i++)
#pragma unroll
                for (int j = 0; j < 4; j++) {
                    s[i][j] = fmaf(qa[i].x, kb4[j].x, s[i][j]);
                    s[i][j] = fmaf(qa[i].y, kb4[j].y, s[i][j]);
                    s[i][j] = fmaf(qa[i].z, kb4[j].z, s[i][j]);
                    s[i][j] = fmaf(qa[i].w, kb4[j].w, s[i][j]);
                }
        }
#pragma unroll
        for (int i = 0; i < 4; i++)
#pragma unroll
            for (int j = 0; j < 4; j++)
                Ss[(r0 + i) * 68 + cbi * 4 + j] = s[i][j];
        __syncthreads();

        // Online softmax: one thread per row
        if (t < 64) {
            const int row = t;
            const int gqi = m0 + row;
            int cmax = gqi - n0 + 1;
            if (cmax > 64) cmax = 64;
            float mold = m_s[row];
            float mx = mold;
            for (int c = 0; c < cmax; c++)
                mx = fmaxf(mx, Ss[row * 68 + c] * ATTN_SCALE);
            float sum = 0.f;
            for (int c = 0; c < 64; c++) {
                float p = (c < cmax) ? __expf(Ss[row * 68 + c] * ATTN_SCALE - mx)
                                     : 0.f;
                Ss[row * 68 + c] = p;
                sum += p;
            }
            float scl = __expf(mold - mx);
            c_s[row] = scl;
            l_s[row] = l_s[row] * scl + sum;
            m_s[row] = mx;
        }
        __syncthreads();

        // Rescale accumulators, then O += P @ V (thread: 4 rows x 8 d)
        float scl_r[4];
#pragma unroll
        for (int i = 0; i < 4; i++) scl_r[i] = c_s[r0 + i];
#pragma unroll
        for (int i = 0; i < 4; i++)
#pragma unroll
            for (int j = 0; j < 8; j++) acc[i][j] *= scl_r[i];

#pragma unroll 2
        for (int c = 0; c < 64; c++) {
            float p[4];
#pragma unroll
            for (int i = 0; i < 4; i++) p[i] = Ss[(r0 + i) * 68 + c];
            float4 v0 = *(float4*)&Vs[c * 132 + cbi * 8];
            float4 v1 = *(float4*)&Vs[c * 132 + cbi * 8 + 4];
#pragma unroll
            for (int i = 0; i < 4; i++) {
                acc[i][0] = fmaf(p[i], v0.x, acc[i][0]);
                acc[i][1] = fmaf(p[i], v0.y, acc[i][1]);
                acc[i][2] = fmaf(p[i], v0.z, acc[i][2]);
                acc[i][3] = fmaf(p[i], v0.w, acc[i][3]);
                acc[i][4] = fmaf(p[i], v1.x, acc[i][4]);
                acc[i][5] = fmaf(p[i], v1.y, acc[i][5]);
                acc[i][6] = fmaf(p[i], v1.z, acc[i][6]);
                acc[i][7] = fmaf(p[i], v1.w, acc[i][7]);
            }
        }
        __syncthreads();
    }

    // Normalize and write out
    float inv[4];
#pragma unroll
    for (int i = 0; i < 4; i++) inv[i] = 1.f / l_s[r0 + i];
#pragma unroll
    for (int i = 0; i < 4; i++) {
        size_t r = (size_t)b * TLEN + m0 + r0 + i;
        *(float4*)(go + r * 128 + cbi * 8) =
            make_float4(acc[i][0] * inv[i], acc[i][1] * inv[i],
                        acc[i][2] * inv[i], acc[i][3] * inv[i]);
        *(float4*)(go + r * 128 + cbi * 8 + 4) =
            make_float4(acc[i][4] * inv[i], acc[i][5] * inv[i],
                        acc[i][6] * inv[i], acc[i][7] * inv[i]);
    }
}

// ---------------------------------------------------------------------------
extern "C" void kernel_launch(void* const* d_in, const int* in_sizes, int n_in,
                              void* d_out, int out_size)
{
    const float* x  = (const float*)d_in[0];
    const float* Wk = (const float*)d_in[1];
    const float* Wq = (const float*)d_in[2];
    const float* Wv = (const float*)d_in[3];
    const float* Wp = (const float*)d_in[4];
    float* out = (float*)d_out;

    float *gq, *gk, *gv, *go;
    cudaGetSymbolAddress((void**)&gq, g_q);
    cudaGetSymbolAddress((void**)&gk, g_k);
    cudaGetSymbolAddress((void**)&gv, g_v);
    cudaGetSymbolAddress((void**)&go, g_o);

    const int smem_bytes = (3 * 64 * 132 + 64 * 68 + 3 * 64) * (int)sizeof(float);
    cudaFuncSetAttribute(flash_attn, cudaFuncAttributeMaxDynamicSharedMemorySize,
                         smem_bytes);

    // QKV projections
    gemm_n128<<<MTOT / 64, 256>>>(x, Wq, gq, EDIM);
    gemm_n128<<<MTOT / 64, 256>>>(x, Wk, gk, EDIM);
    gemm_n128<<<MTOT / 64, 256>>>(x, Wv, gv, EDIM);

    // Causal flash attention
    flash_attn<<<dim3(TLEN / 64, BATCH), 256, smem_bytes>>>(gq, gk, gv, go);

    // Output projection
    gemm_n128<<<MTOT / 64, 256>>>(go, Wp, out, DDIM);
}

// round 2
// speedup vs baseline: 1.0009x; 1.0009x over previous
#include <cuda_runtime.h>
#include <math.h>

// Problem constants
#define BATCH 4
#define TLEN  4096
#define EDIM  1024
#define DDIM  128
#define MTOT  (BATCH*TLEN)          // 16384
#define ATTN_SCALE 0.08838834764831843f  // 1/sqrt(128)

// Scratch (device globals — no allocation allowed)
__device__ float g_q[MTOT*DDIM];
__device__ float g_k[MTOT*DDIM];
__device__ float g_v[MTOT*DDIM];
__device__ float g_o[MTOT*DDIM];

// ---------------------------------------------------------------------------
// C[M,128] = A[M,K] @ B[K,128], row-major. BM=64 per CTA, 256 threads,
// 4x8 register microtile per thread, BK=32.
// ---------------------------------------------------------------------------
__global__ __launch_bounds__(256) void gemm_n128(
    const float* __restrict__ A, const float* __restrict__ B,
    float* __restrict__ C, int K)
{
    __shared__ float As[32][68];    // transposed: As[k][m], pad 4
    __shared__ float Bs[32][132];   // Bs[k][n], pad 4

    const int m0  = blockIdx.x * 64;
    const int t   = threadIdx.x;
    const int rbi = t >> 4;         // 0..15 -> rows rbi*4..+3
    const int cbi = t & 15;         // 0..15 -> cols cbi*8..+7

    float acc[4][8];
#pragma unroll
    for (int i = 0; i < 4; i++)
#pragma unroll
        for (int j = 0; j < 8; j++) acc[i][j] = 0.f;

    for (int k0 = 0; k0 < K; k0 += 32) {
        // A tile 64x32, float4 along k, store transposed
        for (int i = t * 4; i < 64 * 32; i += 1024) {
            int r = i >> 5, c = i & 31;
            float4 v = *(const float4*)(A + (size_t)(m0 + r) * K + k0 + c);
            As[c + 0][r] = v.x; As[c + 1][r] = v.y;
            As[c + 2][r] = v.z; As[c + 3][r] = v.w;
        }
        // B tile 32x128
        for (int i = t * 4; i < 32 * 128; i += 1024) {
            int r = i >> 7, c = i & 127;
            *(float4*)&Bs[r][c] = *(const float4*)(B + (size_t)(k0 + r) * 128 + c);
        }
        __syncthreads();

#pragma unroll 8
        for (int kk = 0; kk < 32; kk++) {
            float4 a4 = *(float4*)&As[kk][rbi * 4];
            float4 b0 = *(float4*)&Bs[kk][cbi * 8];
            float4 b1 = *(float4*)&Bs[kk][cbi * 8 + 4];
            float a[4]  = {a4.x, a4.y, a4.z, a4.w};
            float bb[8] = {b0.x, b0.y, b0.z, b0.w, b1.x, b1.y, b1.z, b1.w};
#pragma unroll
            for (int i = 0; i < 4; i++)
#pragma unroll
                for (int j = 0; j < 8; j++)
                    acc[i][j] = fmaf(a[i], bb[j], acc[i][j]);
        }
        __syncthreads();
    }

#pragma unroll
    for (int i = 0; i < 4; i++) {
        size_t r = (size_t)(m0 + rbi * 4 + i);
        *(float4*)(C + r * 128 + cbi * 8) =
            make_float4(acc[i][0], acc[i][1], acc[i][2], acc[i][3]);
        *(float4*)(C + r * 128 + cbi * 8 + 4) =
            make_float4(acc[i][4], acc[i][5], acc[i][6], acc[i][7]);
    }
}

// ---------------------------------------------------------------------------
// Causal flash attention, fp32. BM=BN=64, D=128. One CTA per (batch, q-tile).
// Dynamic smem: Q(64x132) K(64x132) V(64x132) S(64x68) + m/l/scale(64 each)
// ---------------------------------------------------------------------------
__global__ __launch_bounds__(256) void flash_attn(
    const float* __restrict__ gq, const float* __restrict__ gk,
    const float* __restrict__ gv, float* __restrict__ go)
{
    extern __shared__ float sm[];
    float* Qs  = sm;                 // 64*132
    float* Ks  = Qs + 64 * 132;
    float* Vs  = Ks + 64 * 132;
    float* Ss  = Vs + 64 * 132;      // 64*68
    float* m_s = Ss + 64 * 68;
    float* l_s = m_s + 64;
    float* c_s = l_s + 64;

    const int b  = blockIdx.y;
    const int mt = gridDim.x - 1 - blockIdx.x;  // heavy tiles first
    const int m0 = mt * 64;
    const int t  = threadIdx.x;

    const float* Qb = gq + (size_t)b * TLEN * DDIM;
    const float* Kb = gk + (size_t)b * TLEN * DDIM;
    const float* Vb = gv + (size_t)b * TLEN * DDIM;

    for (int i = t * 4; i < 64 * 128; i += 1024) {
        int r = i >> 7, c = i & 127;
        *(float4*)&Qs[r * 132 + c] =
            *(const float4*)(Qb + (size_t)(m0 + r) * 128 + c);
    }
    if (t < 64) { m_s[t] = -INFINITY; l_s[t] = 0.f; }

    const int rbi = t >> 4, cbi = t & 15;
    const int r0  = rbi * 4;

    float acc[4][8];
#pragma unroll
    for (int i = 0; i < 4; i++)
#pragma unroll
        for (int j = 0; j < 8; j++) acc[i][j] = 0.f;

    __syncthreads();

    for (int nt = 0; nt <= mt; nt++) {
        const int n0 = nt * 64;

        // Load K,V tiles
        for (int i = t * 4; i < 64 * 128; i += 1024) {
            int r = i >> 7, c = i & 127;
            *(float4*)&Ks[r * 132 + c] =
                *(const float4*)(Kb + (size_t)(n0 + r) * 128 + c);
            *(float4*)&Vs[r * 132 + c] =
                *(const float4*)(Vb + (size_t)(n0 + r) * 128 + c);
        }
        __syncthreads();

        // S = Q K^T : thread computes 4x4 tile
        float s[4][4];
#pragma unroll
        for (int i = 0; i < 4; i++)
#pragma unroll
            for (int j = 0; j < 4; j++) s[i][j] = 0.f;

#pragma unroll 4
        for (int kk = 0; kk < 128; kk += 4) {
            float4 qa[4], kb4[4];
#pragma unroll
            for (int i = 0; i < 4; i++)
                qa[i] = *(float4*)&Qs[(r0 + i) * 132 + kk];
#pragma unroll
            for (int j = 0; j < 4; j++)
                kb4[j] = *(float4*)&Ks[(cbi * 4 + j) * 132 + kk];
#pragma unroll
            for (int i = 0; i < 4; i++)
#pragma unroll
                for (int j = 0; j < 4; j++) {
                    s[i][j] = fmaf(qa[i].x, kb4[j].x, s[i][j]);
                    s[i][j] = fmaf(qa[i].y, kb4[j].y, s[i][j]);
                    s[i][j] = fmaf(qa[i].z, kb4[j].z, s[i][j]);
                    s[i][j] = fmaf(qa[i].w, kb4[j].w, s[i][j]);
                }
        }
#pragma unroll
        for (int i = 0; i < 4; i++)
#pragma unroll
            for (int j = 0; j < 4; j++)
                Ss[(r0 + i) * 68 + cbi * 4 + j] = s[i][j];
        __syncthreads();

        // Online softmax: one thread per row
        if (t < 64) {
            const int row = t;
            const int gqi = m0 + row;
            int cmax = gqi - n0 + 1;
            if (cmax > 64) cmax = 64;
            float mold = m_s[row];
            float mx = mold;
            for (int c = 0; c < cmax; c++)
                mx = fmaxf(mx, Ss[row * 68 + c] * ATTN_SCALE);
            float sum = 0.f;
            for (int c = 0; c < 64; c++) {
                float p = (c < cmax) ? __expf(Ss[row * 68 + c] * ATTN_SCALE - mx)
                                     : 0.f;
                Ss[row * 68 + c] = p;
                sum += p;
            }
            float scl = __expf(mold - mx);
            c_s[row] = scl;
            l_s[row] = l_s[row] * scl + sum;
            m_s[row] = mx;
        }
        __syncthreads();

        // Rescale accumulators, then O += P @ V (thread: 4 rows x 8 d)
        float scl_r[4];
#pragma unroll
        for (int i = 0; i < 4; i++) scl_r[i] = c_s[r0 + i];
#pragma unroll
        for (int i = 0; i < 4; i++)
#pragma unroll
            for (int j = 0; j < 8; j++) acc[i][j] *= scl_r[i];

#pragma unroll 2
        for (int c = 0; c < 64; c++) {
            float p[4];
#pragma unroll
            for (int i = 0; i < 4; i++) p[i] = Ss[(r0 + i) * 68 + c];
            float4 v0 = *(float4*)&Vs[c * 132 + cbi * 8];
            float4 v1 = *(float4*)&Vs[c * 132 + cbi * 8 + 4];
#pragma unroll
            for (int i = 0; i < 4; i++) {
                acc[i][0] = fmaf(p[i], v0.x, acc[i][0]);
                acc[i][1] = fmaf(p[i], v0.y, acc[i][1]);
                acc[i][2] = fmaf(p[i], v0.z, acc[i][2]);
                acc[i][3] = fmaf(p[i], v0.w, acc[i][3]);
                acc[i][4] = fmaf(p[i], v1.x, acc[i][4]);
                acc[i][5] = fmaf(p[i], v1.y, acc[i][5]);
                acc[i][6] = fmaf(p[i], v1.z, acc[i][6]);
                acc[i][7] = fmaf(p[i], v1.w, acc[i][7]);
            }
        }
        __syncthreads();
    }

    // Normalize and write out
    float inv[4];
#pragma unroll
    for (int i = 0; i < 4; i++) inv[i] = 1.f / l_s[r0 + i];
#pragma unroll
    for (int i = 0; i < 4; i++) {
        size_t r = (size_t)b * TLEN + m0 + r0 + i;
        *(float4*)(go + r * 128 + cbi * 8) =
            make_float4(acc[i][0] * inv[i], acc[i][1] * inv[i],
                        acc[i][2] * inv[i], acc[i][3] * inv[i]);
        *(float4*)(go + r * 128 + cbi * 8 + 4) =
            make_float4(acc[i][4] * inv[i], acc[i][5] * inv[i],
                        acc[i][6] * inv[i], acc[i][7] * inv[i]);
    }
}

// ---------------------------------------------------------------------------
extern "C" void kernel_launch(void* const* d_in, const int* in_sizes, int n_in,
                              void* d_out, int out_size)
{
    const float* x  = (const float*)d_in[0];
    const float* Wk = (const float*)d_in[1];
    const float* Wq = (const float*)d_in[2];
    const float* Wv = (const float*)d_in[3];
    const float* Wp = (const float*)d_in[4];
    float* out = (float*)d_out;

    float *gq, *gk, *gv, *go;
    cudaGetSymbolAddress((void**)&gq, g_q);
    cudaGetSymbolAddress((void**)&gk, g_k);
    cudaGetSymbolAddress((void**)&gv, g_v);
    cudaGetSymbolAddress((void**)&go, g_o);

    const int smem_bytes = (3 * 64 * 132 + 64 * 68 + 3 * 64) * (int)sizeof(float);
    cudaFuncSetAttribute(flash_attn, cudaFuncAttributeMaxDynamicSharedMemorySize,
                         smem_bytes);

    // QKV projections
    gemm_n128<<<MTOT / 64, 256>>>(x, Wq, gq, EDIM);
    gemm_n128<<<MTOT / 64, 256>>>(x, Wk, gk, EDIM);
    gemm_n128<<<MTOT / 64, 256>>>(x, Wv, gv, EDIM);

    // Causal flash attention
    flash_attn<<<dim3(TLEN / 64, BATCH), 256, smem_bytes>>>(gq, gk, gv, go);

    // Output projection
    gemm_n128<<<MTOT / 64, 256>>>(go, Wp, out, DDIM);
}

// round 4
// speedup vs baseline: 2.2930x; 2.2909x over previous
#include <cuda_runtime.h>
#include <cuda_bf16.h>
#include <math.h>
#include <stdint.h>

#define BATCH 4
#define TLEN  4096
#define EDIM  1024
#define DDIM  128
#define MTOT  (BATCH*TLEN)
#define ATTN_SCALE 0.08838834764831843f

// ---------------- device scratch ----------------
__device__ __nv_bfloat16 g_xh[(size_t)MTOT*EDIM];
__device__ __nv_bfloat16 g_xl[(size_t)MTOT*EDIM];
__device__ __nv_bfloat16 g_wth[3*DDIM*EDIM];   // [w][n][k] transposed hi
__device__ __nv_bfloat16 g_wtl[3*DDIM*EDIM];
__device__ __nv_bfloat16 g_wpth[DDIM*DDIM];    // Wp^T [n][k] hi
__device__ __nv_bfloat16 g_wptl[DDIM*DDIM];
__device__ float g_q[(size_t)MTOT*DDIM];
__device__ float g_k[(size_t)MTOT*DDIM];
__device__ float g_v[(size_t)MTOT*DDIM];
__device__ float g_o[(size_t)MTOT*DDIM];
__device__ __nv_bfloat16 g_oh[(size_t)MTOT*DDIM];
__device__ __nv_bfloat16 g_ol[(size_t)MTOT*DDIM];

// ---------------- helpers ----------------
__device__ __forceinline__ uint32_t su32(const void* p) {
    return (uint32_t)__cvta_generic_to_shared(p);
}
__device__ __forceinline__ void cp16(uint32_t dst, const void* src) {
    asm volatile("cp.async.cg.shared.global [%0], [%1], 16;" :: "r"(dst), "l"(src));
}
#define CP_COMMIT() asm volatile("cp.async.commit_group;" ::: "memory")
#define CP_WAIT0()  asm volatile("cp.async.wait_group 0;" ::: "memory")

__device__ __forceinline__ uint32_t swz(uint32_t off) {
    return off ^ ((off >> 3) & 0x70);
}

#define LDSM4(r, addr) \
    asm volatile("ldmatrix.sync.aligned.m8n8.x4.shared.b16 {%0,%1,%2,%3}, [%4];" \
        : "=r"((r)[0]), "=r"((r)[1]), "=r"((r)[2]), "=r"((r)[3]) : "r"(addr))

#define MMA16816(d, a, b0, b1) \
    asm volatile("mma.sync.aligned.m16n8k16.row.col.f32.bf16.bf16.f32 " \
        "{%0,%1,%2,%3}, {%4,%5,%6,%7}, {%8,%9}, {%0,%1,%2,%3};" \
        : "+f"((d)[0]), "+f"((d)[1]), "+f"((d)[2]), "+f"((d)[3]) \
        : "r"((a)[0]), "r"((a)[1]), "r"((a)[2]), "r"((a)[3]), "r"(b0), "r"(b1))

__device__ __forceinline__ float2 ffma2(float2 a, float2 b, float2 c) {
    unsigned long long A = *(unsigned long long*)&a, B = *(unsigned long long*)&b,
                       C = *(unsigned long long*)&c, D;
    asm("fma.rn.f32x2 %0, %1, %2, %3;" : "=l"(D) : "l"(A), "l"(B), "l"(C));
    return *(float2*)&D;
}

// ---------------- split fp32 -> bf16 hi/lo ----------------
__global__ __launch_bounds__(256) void split_f32(const float* __restrict__ s,
                                                 __nv_bfloat16* __restrict__ h,
                                                 __nv_bfloat16* __restrict__ l, int n4) {
    int idx = blockIdx.x * 256 + threadIdx.x;
    if (idx >= n4) return;
    float4 v = ((const float4*)s)[idx];
    float vv[4] = {v.x, v.y, v.z, v.w};
    __nv_bfloat16 hh[4], ll[4];
#pragma unroll
    for (int i = 0; i < 4; i++) {
        hh[i] = __float2bfloat16(vv[i]);
        ll[i] = __float2bfloat16(vv[i] - __bfloat162float(hh[i]));
    }
    ((__nv_bfloat162*)h)[idx*2]   = __nv_bfloat162(hh[0], hh[1]);
    ((__nv_bfloat162*)h)[idx*2+1] = __nv_bfloat162(hh[2], hh[3]);
    ((__nv_bfloat162*)l)[idx*2]   = __nv_bfloat162(ll[0], ll[1]);
    ((__nv_bfloat162*)l)[idx*2+1] = __nv_bfloat162(ll[2], ll[3]);
}

// ---------------- transpose + split weights ----------------
__global__ __launch_bounds__(256) void convert_w(
    const float* __restrict__ wq, const float* __restrict__ wk,
    const float* __restrict__ wv, const float* __restrict__ wp,
    __nv_bfloat16* __restrict__ wth, __nv_bfloat16* __restrict__ wtl,
    __nv_bfloat16* __restrict__ wpth, __nv_bfloat16* __restrict__ wptl) {
    int idx = blockIdx.x * 256 + threadIdx.x;
    if (idx < 3 * DDIM * EDIM) {
        int k = idx & (EDIM - 1), n = (idx >> 10) & (DDIM - 1), w = idx >> 17;
        const float* W = (w == 0) ? wq : ((w == 1) ? wk : wv);
        float v = W[(size_t)k * DDIM + n];
        __nv_bfloat16 h = __float2bfloat16(v);
        wth[idx] = h; wtl[idx] = __float2bfloat16(v - __bfloat162float(h));
    }
    if (idx < DDIM * DDIM) {
        int k = idx & 127, n = idx >> 7;
        float v = wp[(size_t)k * DDIM + n];
        __nv_bfloat16 h = __float2bfloat16(v);
        wpth[idx] = h; wptl[idx] = __float2bfloat16(v - __bfloat162float(h));
    }
}

// ---------------------------------------------------------------------------
// C[M,128] = A[M,K] @ Bt[128,K]^T via mma.sync bf16 split hi/lo (3 passes).
// BM=128, BN=128, BK=64, 256 threads (8 warps as 4m x 2n), SW128 smem.
// ---------------------------------------------------------------------------
__global__ __launch_bounds__(256) void mm_bf16(
    const __nv_bfloat16* __restrict__ Ah, const __nv_bfloat16* __restrict__ Al,
    const __nv_bfloat16* __restrict__ Bh, const __nv_bfloat16* __restrict__ Bl,
    float* __restrict__ C, int K) {
    extern __shared__ char smem[];
    const uint32_t sb = su32(smem);
    const uint32_t oAh = 0, oAl = 16384, oBh = 32768, oBl = 49152;
    const int tid = threadIdx.x, lane = tid & 31, warp = tid >> 5;
    const int wm = (warp & 3) * 32;     // warp m offset
    const int wn = (warp >> 2) * 64;    // warp n offset
    const int m0 = blockIdx.x * 128;

    float acc[2][8][4];
#pragma unroll
    for (int i = 0; i < 2; i++)
#pragma unroll
        for (int j = 0; j < 8; j++)
#pragma unroll
            for (int u = 0; u < 4; u++) acc[i][j][u] = 0.f;

    for (int k0 = 0; k0 < K; k0 += 64) {
        for (int u = tid; u < 1024; u += 256) {
            int r = u >> 3, c = u & 7;
            uint32_t sw = swz((uint32_t)(r * 128 + c * 16));
            size_t ao = (size_t)(m0 + r) * K + k0 + c * 8;
            size_t bo = (size_t)r * K + k0 + c * 8;
            cp16(sb + oAh + sw, Ah + ao);
            cp16(sb + oAl + sw, Al + ao);
            cp16(sb + oBh + sw, Bh + bo);
            cp16(sb + oBl + sw, Bl + bo);
        }
        CP_COMMIT(); CP_WAIT0();
        __syncthreads();

#pragma unroll
        for (int ks = 0; ks < 4; ks++) {
            const int kb = ks * 16;
            uint32_t a_h[2][4], a_l[2][4];
#pragma unroll
            for (int mt = 0; mt < 2; mt++) {
                int row = wm + mt * 16 + (lane & 15);
                int colb = (kb + ((lane >> 4) * 8)) * 2;
                uint32_t sw = swz((uint32_t)(row * 128 + colb));
                LDSM4(a_h[mt], sb + oAh + sw);
                LDSM4(a_l[mt], sb + oAl + sw);
            }
            uint32_t b_h[4][4], b_l[4][4];
#pragma unroll
            for (int np = 0; np < 4; np++) {
                int row = wn + np * 16 + ((lane >> 4) * 8) + (lane & 7);
                int colb = (kb + (((lane >> 3) & 1) * 8)) * 2;
                uint32_t sw = swz((uint32_t)(row * 128 + colb));
                LDSM4(b_h[np], sb + oBh + sw);
                LDSM4(b_l[np], sb + oBl + sw);
            }
#pragma unroll
            for (int mt = 0; mt < 2; mt++)
#pragma unroll
                for (int np = 0; np < 4; np++) {
                    MMA16816(acc[mt][np*2],   a_h[mt], b_h[np][0], b_h[np][1]);
                    MMA16816(acc[mt][np*2],   a_l[mt], b_h[np][0], b_h[np][1]);
                    MMA16816(acc[mt][np*2],   a_h[mt], b_l[np][0], b_l[np][1]);
                    MMA16816(acc[mt][np*2+1], a_h[mt], b_h[np][2], b_h[np][3]);
                    MMA16816(acc[mt][np*2+1], a_l[mt], b_h[np][2], b_h[np][3]);
                    MMA16816(acc[mt][np*2+1], a_h[mt], b_l[np][2], b_l[np][3]);
                }
        }
        __syncthreads();
    }

#pragma unroll
    for (int mt = 0; mt < 2; mt++)
#pragma unroll
        for (int j = 0; j < 8; j++) {
            int row = m0 + wm + mt * 16 + (lane >> 2);
            int col = wn + j * 8 + (lane & 3) * 2;
            *(float2*)(C + (size_t)row * 128 + col) =
                make_float2(acc[mt][j][0], acc[mt][j][1]);
            *(float2*)(C + (size_t)(row + 8) * 128 + col) =
                make_float2(acc[mt][j][2], acc[mt][j][3]);
        }
}

// ---------------- flash attention (fp32, conflict-free, f32x2) ----------------
__global__ __launch_bounds__(256) void flash_attn(
    const float* __restrict__ gq, const float* __restrict__ gk,
    const float* __restrict__ gv, float* __restrict__ go) {
    extern __shared__ float sm[];
    float* Qs = sm;                  // 64*132
    float* Ks = Qs + 64 * 132;
    float* Vs = Ks + 64 * 132;
    float* Ss = Vs + 64 * 132;       // 64*68
    float* m_s = Ss + 64 * 68;
    float* l_s = m_s + 64;
    float* c_s = l_s + 64;

    const int b = blockIdx.y;
    const int mt = gridDim.x - 1 - blockIdx.x;   // heavy tiles first
    const int m0 = mt * 64;
    const int t = threadIdx.x;
    const int rbi = t >> 4, cbi = t & 15, r0 = rbi * 4;

    const float* Qb = gq + (size_t)b * TLEN * DDIM;
    const float* Kb = gk + (size_t)b * TLEN * DDIM;
    const float* Vb = gv + (size_t)b * TLEN * DDIM;

    for (int i = t * 4; i < 64 * 128; i += 1024) {
        int r = i >> 7, c = i & 127;
        float4 q = *(const float4*)(Qb + (size_t)(m0 + r) * 128 + c);
        q.x *= ATTN_SCALE; q.y *= ATTN_SCALE; q.z *= ATTN_SCALE; q.w *= ATTN_SCALE;
        *(float4*)&Qs[r * 132 + c] = q;
    }
    if (t < 64) { m_s[t] = -INFINITY; l_s[t] = 0.f; }

    float2 acc[4][4];
#pragma unroll
    for (int i = 0; i < 4; i++)
#pragma unroll
        for (int j = 0; j < 4; j++) acc[i][j] = make_float2(0.f, 0.f);

    __syncthreads();

    for (int nt = 0; nt <= mt; nt++) {
        const int n0 = nt * 64;
        for (int i = t * 4; i < 64 * 128; i += 1024) {
            int r = i >> 7, c = i & 127;
            *(float4*)&Ks[r * 132 + c] = *(const float4*)(Kb + (size_t)(n0 + r) * 128 + c);
            *(float4*)&Vs[r * 132 + c] = *(const float4*)(Vb + (size_t)(n0 + r) * 128 + c);
        }
        __syncthreads();

        // S = Q K^T, thread cols = cbi + 16*j (conflict-free K reads)
        float2 s2[4][4];
#pragma unroll
        for (int i = 0; i < 4; i++)
#pragma unroll
            for (int j = 0; j < 4; j++) s2[i][j] = make_float2(0.f, 0.f);
#pragma unroll 2
        for (int kk = 0; kk < 128; kk += 4) {
            float4 q4[4], k4[4];
#pragma unroll
            for (int i = 0; i < 4; i++) q4[i] = *(float4*)&Qs[(r0 + i) * 132 + kk];
#pragma unroll
            for (int j = 0; j < 4; j++) k4[j] = *(float4*)&Ks[(cbi + 16 * j) * 132 + kk];
#pragma unroll
            for (int i = 0; i < 4; i++)
#pragma unroll
                for (int j = 0; j < 4; j++) {
                    s2[i][j] = ffma2(make_float2(q4[i].x, q4[i].y),
                                     make_float2(k4[j].x, k4[j].y), s2[i][j]);
                    s2[i][j] = ffma2(make_float2(q4[i].z, q4[i].w),
                                     make_float2(k4[j].z, k4[j].w), s2[i][j]);
                }
        }
#pragma unroll
        for (int i = 0; i < 4; i++)
#pragma unroll
            for (int j = 0; j < 4; j++)
                Ss[(r0 + i) * 68 + cbi + 16 * j] = s2[i][j].x + s2[i][j].y;
        __syncthreads();

        // softmax: 4 threads per row
        {
            const int row = t >> 2, sub = t & 3;
            int cmax = m0 + row - n0 + 1; if (cmax > 64) cmax = 64;
            float mold = m_s[row];
            float mx = -INFINITY;
#pragma unroll 4
            for (int c = sub * 16; c < sub * 16 + 16; c++)
                if (c < cmax) mx = fmaxf(mx, Ss[row * 68 + c]);
            mx = fmaxf(mx, __shfl_xor_sync(0xffffffffu, mx, 1));
            mx = fmaxf(mx, __shfl_xor_sync(0xffffffffu, mx, 2));
            mx = fmaxf(mx, mold);
            float sum = 0.f;
#pragma unroll 4
            for (int c = sub * 16; c < sub * 16 + 16; c++) {
                float p = (c < cmax) ? __expf(Ss[row * 68 + c] - mx) : 0.f;
                Ss[row * 68 + c] = p;
                sum += p;
            }
            sum += __shfl_xor_sync(0xffffffffu, sum, 1);
            sum += __shfl_xor_sync(0xffffffffu, sum, 2);
            if (sub == 0) {
                float scl = __expf(mold - mx);
                c_s[row] = scl;
                l_s[row] = l_s[row] * scl + sum;
                m_s[row] = mx;
            }
        }
        __syncthreads();

        // rescale + O += P @ V  (thread d-cols: 4*cbi..+3 and 64+4*cbi..+3)
        {
            float scl_r[4];
#pragma unroll
            for (int i = 0; i < 4; i++) scl_r[i] = c_s[r0 + i];
#pragma unroll
            for (int i = 0; i < 4; i++)
#pragma unroll
                for (int j = 0; j < 4; j++) {
                    acc[i][j].x *= scl_r[i]; acc[i][j].y *= scl_r[i];
                }
#pragma unroll 2
            for (int c4 = 0; c4 < 16; c4++) {
                float4 s4[4];
#pragma unroll
                for (int i = 0; i < 4; i++) s4[i] = *(float4*)&Ss[(r0 + i) * 68 + c4 * 4];
#pragma unroll
                for (int u = 0; u < 4; u++) {
                    int c = c4 * 4 + u;
                    float4 v0 = *(float4*)&Vs[c * 132 + cbi * 4];
                    float4 v1 = *(float4*)&Vs[c * 132 + cbi * 4 + 64];
#pragma unroll
                    for (int i = 0; i < 4; i++) {
                        float p = (u == 0) ? s4[i].x : (u == 1) ? s4[i].y
                                : (u == 2) ? s4[i].z : s4[i].w;
                        float2 pd = make_float2(p, p);
                        acc[i][0] = ffma2(pd, make_float2(v0.x, v0.y), acc[i][0]);
                        acc[i][1] = ffma2(pd, make_float2(v0.z, v0.w), acc[i][1]);
                        acc[i][2] = ffma2(pd, make_float2(v1.x, v1.y), acc[i][2]);
                        acc[i][3] = ffma2(pd, make_float2(v1.z, v1.w), acc[i][3]);
                    }
                }
            }
        }
        __syncthreads();
    }

    float inv[4];
#pragma unroll
    for (int i = 0; i < 4; i++) inv[i] = 1.f / l_s[r0 + i];
#pragma unroll
    for (int i = 0; i < 4; i++) {
        size_t r = (size_t)b * TLEN + m0 + r0 + i;
        *(float4*)(go + r * 128 + cbi * 4) =
            make_float4(acc[i][0].x * inv[i], acc[i][0].y * inv[i],
                        acc[i][1].x * inv[i], acc[i][1].y * inv[i]);
        *(float4*)(go + r * 128 + cbi * 4 + 64) =
            make_float4(acc[i][2].x * inv[i], acc[i][2].y * inv[i],
                        acc[i][3].x * inv[i], acc[i][3].y * inv[i]);
    }
}

// ---------------------------------------------------------------------------
extern "C" void kernel_launch(void* const* d_in, const int* in_sizes, int n_in,
                              void* d_out, int out_size) {
    const float* x  = (const float*)d_in[0];
    const float* Wk = (const float*)d_in[1];
    const float* Wq = (const float*)d_in[2];
    const float* Wv = (const float*)d_in[3];
    const float* Wp = (const float*)d_in[4];
    float* out = (float*)d_out;

    __nv_bfloat16 *xh, *xl, *wth, *wtl, *wpth, *wptl, *oh, *ol;
    float *gq, *gk, *gv, *go;
    cudaGetSymbolAddress((void**)&xh, g_xh);   cudaGetSymbolAddress((void**)&xl, g_xl);
    cudaGetSymbolAddress((void**)&wth, g_wth); cudaGetSymbolAddress((void**)&wtl, g_wtl);
    cudaGetSymbolAddress((void**)&wpth, g_wpth); cudaGetSymbolAddress((void**)&wptl, g_wptl);
    cudaGetSymbolAddress((void**)&oh, g_oh);   cudaGetSymbolAddress((void**)&ol, g_ol);
    cudaGetSymbolAddress((void**)&gq, g_q);    cudaGetSymbolAddress((void**)&gk, g_k);
    cudaGetSymbolAddress((void**)&gv, g_v);    cudaGetSymbolAddress((void**)&go, g_o);

    const int mm_smem = 65536;
    const int fa_smem = (3 * 64 * 132 + 64 * 68 + 3 * 64) * (int)sizeof(float);
    cudaFuncSetAttribute(mm_bf16, cudaFuncAttributeMaxDynamicSharedMemorySize, mm_smem);
    cudaFuncSetAttribute(flash_attn, cudaFuncAttributeMaxDynamicSharedMemorySize, fa_smem);

    split_f32<<<MTOT * EDIM / 4 / 256, 256>>>(x, xh, xl, MTOT * EDIM / 4);
    convert_w<<<(3 * DDIM * EDIM + 255) / 256, 256>>>(Wq, Wk, Wv, Wp, wth, wtl, wpth, wptl);

    mm_bf16<<<MTOT / 128, 256, mm_smem>>>(xh, xl, wth,                     wtl,                     gq, EDIM);
    mm_bf16<<<MTOT / 128, 256, mm_smem>>>(xh, xl, wth + 1 * DDIM * EDIM,   wtl + 1 * DDIM * EDIM,   gk, EDIM);
    mm_bf16<<<MTOT / 128, 256, mm_smem>>>(xh, xl, wth + 2 * DDIM * EDIM,   wtl + 2 * DDIM * EDIM,   gv, EDIM);

    flash_attn<<<dim3(TLEN / 64, BATCH), 256, fa_smem>>>(gq, gk, gv, go);

    split_f32<<<MTOT * DDIM / 4 / 256, 256>>>(go, oh, ol, MTOT * DDIM / 4);
    mm_bf16<<<MTOT / 128, 256, mm_smem>>>(oh, ol, wpth, wptl, out, DDIM);
}

// round 5
// speedup vs baseline: 6.0498x; 2.6383x over previous
#include <cuda_runtime.h>
#include <cuda_bf16.h>
#include <math.h>
#include <stdint.h>

#define BATCH 4
#define TLEN  4096
#define EDIM  1024
#define DDIM  128
#define MTOT  (BATCH*TLEN)
typedef __nv_bfloat16 bf16;

// q pre-scale: 1/sqrt(128) * log2(e)
#define QSCALE ((float)(0.08838834764831843 * 1.4426950408889634))

// ---------------- device scratch ----------------
__device__ bf16 g_xh[(size_t)MTOT*EDIM];
__device__ bf16 g_xl[(size_t)MTOT*EDIM];
__device__ bf16 g_wth[3*DDIM*EDIM];
__device__ bf16 g_wtl[3*DDIM*EDIM];
__device__ bf16 g_wpth[DDIM*DDIM];
__device__ bf16 g_wptl[DDIM*DDIM];
__device__ bf16 g_qh[(size_t)MTOT*DDIM], g_ql[(size_t)MTOT*DDIM];
__device__ bf16 g_kh[(size_t)MTOT*DDIM], g_kl[(size_t)MTOT*DDIM];
__device__ bf16 g_vh[(size_t)MTOT*DDIM], g_vl[(size_t)MTOT*DDIM];
__device__ bf16 g_oh[(size_t)MTOT*DDIM], g_ol[(size_t)MTOT*DDIM];

// ---------------- helpers ----------------
__device__ __forceinline__ uint32_t su32(const void* p) {
    return (uint32_t)__cvta_generic_to_shared(p);
}
__device__ __forceinline__ void cp16(uint32_t dst, const void* src) {
    asm volatile("cp.async.cg.shared.global [%0], [%1], 16;" :: "r"(dst), "l"(src));
}
#define CP_COMMIT() asm volatile("cp.async.commit_group;" ::: "memory")
template<int N> __device__ __forceinline__ void cp_wait() {
    asm volatile("cp.async.wait_group %0;" :: "n"(N) : "memory");
}
__device__ __forceinline__ uint32_t swz(uint32_t off) {       // 128B rows
    return off ^ ((off >> 3) & 0x70);
}
__device__ __forceinline__ uint32_t sw256(int r, int cb) {    // 256B rows
    return (uint32_t)(r * 256 + (cb ^ ((r & 7) << 4)));
}
#define LDSM4(r, addr) \
    asm volatile("ldmatrix.sync.aligned.m8n8.x4.shared.b16 {%0,%1,%2,%3}, [%4];" \
        : "=r"((r)[0]), "=r"((r)[1]), "=r"((r)[2]), "=r"((r)[3]) : "r"(addr))
#define LDSM4T(r, addr) \
    asm volatile("ldmatrix.sync.aligned.m8n8.x4.trans.shared.b16 {%0,%1,%2,%3}, [%4];" \
        : "=r"((r)[0]), "=r"((r)[1]), "=r"((r)[2]), "=r"((r)[3]) : "r"(addr))
#define MMA16816(d, a, b0, b1) \
    asm volatile("mma.sync.aligned.m16n8k16.row.col.f32.bf16.bf16.f32 " \
        "{%0,%1,%2,%3}, {%4,%5,%6,%7}, {%8,%9}, {%0,%1,%2,%3};" \
        : "+f"((d)[0]), "+f"((d)[1]), "+f"((d)[2]), "+f"((d)[3]) \
        : "r"((a)[0]), "r"((a)[1]), "r"((a)[2]), "r"((a)[3]), "r"(b0), "r"(b1))

__device__ __forceinline__ uint32_t pk2(float lo, float hi) { // {low:lo, high:hi}
    uint32_t r;
    asm("cvt.rn.bf16x2.f32 %0, %1, %2;" : "=r"(r) : "f"(hi), "f"(lo));
    return r;
}
__device__ __forceinline__ float lo_f(uint32_t h) { return __uint_as_float(h << 16); }
__device__ __forceinline__ float hi_f(uint32_t h) { return __uint_as_float(h & 0xffff0000u); }
__device__ __forceinline__ float ex2(float x) {
    float y; asm("ex2.approx.f32 %0, %1;" : "=f"(y) : "f"(x)); return y;
}

// ---------------- split fp32 -> bf16 hi/lo ----------------
__global__ __launch_bounds__(256) void split_f32(const float* __restrict__ s,
                                                 bf16* __restrict__ h,
                                                 bf16* __restrict__ l, int n4) {
    int idx = blockIdx.x * 256 + threadIdx.x;
    if (idx >= n4) return;
    float4 v = ((const float4*)s)[idx];
    float vv[4] = {v.x, v.y, v.z, v.w};
    uint32_t h0 = pk2(vv[0], vv[1]), h1 = pk2(vv[2], vv[3]);
    uint32_t l0 = pk2(vv[0] - lo_f(h0), vv[1] - hi_f(h0));
    uint32_t l1 = pk2(vv[2] - lo_f(h1), vv[3] - hi_f(h1));
    ((uint32_t*)h)[idx*2] = h0; ((uint32_t*)h)[idx*2+1] = h1;
    ((uint32_t*)l)[idx*2] = l0; ((uint32_t*)l)[idx*2+1] = l1;
}

// ---------------- transpose + split weights ----------------
__global__ __launch_bounds__(256) void convert_w(
    const float* __restrict__ wq, const float* __restrict__ wk,
    const float* __restrict__ wv, const float* __restrict__ wp,
    bf16* __restrict__ wth, bf16* __restrict__ wtl,
    bf16* __restrict__ wpth, bf16* __restrict__ wptl) {
    int idx = blockIdx.x * 256 + threadIdx.x;
    if (idx < 3 * DDIM * EDIM) {
        int k = idx & (EDIM - 1), n = (idx >> 10) & (DDIM - 1), w = idx >> 17;
        const float* W = (w == 0) ? wq : ((w == 1) ? wk : wv);
        float v = W[(size_t)k * DDIM + n];
        bf16 h = __float2bfloat16(v);
        wth[idx] = h; wtl[idx] = __float2bfloat16(v - __bfloat162float(h));
    }
    if (idx < DDIM * DDIM) {
        int k = idx & 127, n = idx >> 7;
        float v = wp[(size_t)k * DDIM + n];
        bf16 h = __float2bfloat16(v);
        wpth[idx] = h; wptl[idx] = __float2bfloat16(v - __bfloat162float(h));
    }
}

// ---------------------------------------------------------------------------
// C[M,128] = A[M,K] @ Bt[128,K]^T, split bf16, 3-pass, double-buffered.
// SPLIT=1: write bf16 hi/lo with scale. SPLIT=0: write fp32.
// ---------------------------------------------------------------------------
template<int SPLIT>
__global__ __launch_bounds__(256) void mm_bf16(
    const bf16* __restrict__ Ah, const bf16* __restrict__ Al,
    const bf16* __restrict__ Bh, const bf16* __restrict__ Bl,
    float* __restrict__ C, bf16* __restrict__ Ch, bf16* __restrict__ Cl,
    float oscale, int K) {
    extern __shared__ char smem[];
    const uint32_t sb = su32(smem);
    const int tid = threadIdx.x, lane = tid & 31, warp = tid >> 5;
    const int wm = (warp & 3) * 32, wn = (warp >> 2) * 64;
    const int m0 = blockIdx.x * 128;

    float acc[2][8][4];
#pragma unroll
    for (int i = 0; i < 2; i++)
#pragma unroll
        for (int j = 0; j < 8; j++)
#pragma unroll
            for (int u = 0; u < 4; u++) acc[i][j][u] = 0.f;

    auto prefetch = [&](int k0, int st) {
        uint32_t base = sb + st * 65536;
        for (int u = tid; u < 1024; u += 256) {
            int r = u >> 3, c = u & 7;
            uint32_t sw = swz((uint32_t)(r * 128 + c * 16));
            size_t ao = (size_t)(m0 + r) * K + k0 + c * 8;
            size_t bo = (size_t)r * K + k0 + c * 8;
            cp16(base + sw, Ah + ao);
            cp16(base + 16384 + sw, Al + ao);
            cp16(base + 32768 + sw, Bh + bo);
            cp16(base + 49152 + sw, Bl + bo);
        }
        CP_COMMIT();
    };

    const int nck = K / 64;
    prefetch(0, 0);
    for (int ck = 0; ck < nck; ck++) {
        if (ck + 1 < nck) { prefetch((ck + 1) * 64, (ck + 1) & 1); cp_wait<1>(); }
        else cp_wait<0>();
        __syncthreads();
        const uint32_t base = sb + (ck & 1) * 65536;
        const uint32_t oAh = base, oAl = base + 16384, oBh = base + 32768, oBl = base + 49152;
#pragma unroll
        for (int ks = 0; ks < 4; ks++) {
            const int kb = ks * 16;
            uint32_t a_h[2][4], a_l[2][4];
#pragma unroll
            for (int mt = 0; mt < 2; mt++) {
                int row = wm + mt * 16 + (lane & 15);
                int colb = (kb + ((lane >> 4) * 8)) * 2;
                uint32_t sw = swz((uint32_t)(row * 128 + colb));
                LDSM4(a_h[mt], oAh + sw);
                LDSM4(a_l[mt], oAl + sw);
            }
            uint32_t b_h[4][4], b_l[4][4];
#pragma unroll
            for (int np = 0; np < 4; np++) {
                int row = wn + np * 16 + ((lane >> 4) * 8) + (lane & 7);
                int colb = (kb + (((lane >> 3) & 1) * 8)) * 2;
                uint32_t sw = swz((uint32_t)(row * 128 + colb));
                LDSM4(b_h[np], oBh + sw);
                LDSM4(b_l[np], oBl + sw);
            }
#pragma unroll
            for (int mt = 0; mt < 2; mt++)
#pragma unroll
                for (int np = 0; np < 4; np++) {
                    MMA16816(acc[mt][np*2],   a_h[mt], b_h[np][0], b_h[np][1]);
                    MMA16816(acc[mt][np*2],   a_l[mt], b_h[np][0], b_h[np][1]);
                    MMA16816(acc[mt][np*2],   a_h[mt], b_l[np][0], b_l[np][1]);
                    MMA16816(acc[mt][np*2+1], a_h[mt], b_h[np][2], b_h[np][3]);
                    MMA16816(acc[mt][np*2+1], a_l[mt], b_h[np][2], b_h[np][3]);
                    MMA16816(acc[mt][np*2+1], a_h[mt], b_l[np][2], b_l[np][3]);
                }
        }
        __syncthreads();
    }

#pragma unroll
    for (int mt = 0; mt < 2; mt++)
#pragma unroll
        for (int j = 0; j < 8; j++) {
            int row = m0 + wm + mt * 16 + (lane >> 2);
            int col = wn + j * 8 + (lane & 3) * 2;
            if (SPLIT) {
                float v0 = acc[mt][j][0] * oscale, v1 = acc[mt][j][1] * oscale;
                float v2 = acc[mt][j][2] * oscale, v3 = acc[mt][j][3] * oscale;
                uint32_t h0 = pk2(v0, v1), h1 = pk2(v2, v3);
                *(uint32_t*)(Ch + (size_t)row * 128 + col) = h0;
                *(uint32_t*)(Cl + (size_t)row * 128 + col) = pk2(v0 - lo_f(h0), v1 - hi_f(h0));
                *(uint32_t*)(Ch + (size_t)(row + 8) * 128 + col) = h1;
                *(uint32_t*)(Cl + (size_t)(row + 8) * 128 + col) = pk2(v2 - lo_f(h1), v3 - hi_f(h1));
            } else {
                *(float2*)(C + (size_t)row * 128 + col) =
                    make_float2(acc[mt][j][0], acc[mt][j][1]);
                *(float2*)(C + (size_t)(row + 8) * 128 + col) =
                    make_float2(acc[mt][j][2], acc[mt][j][3]);
            }
        }
}

// ---------------------------------------------------------------------------
// Flash attention on mma.sync bf16 split. BM=64, BN=64, D=128.
// 128 threads (4 warps x 16 rows), 2 CTAs/SM, Q resident, K/V single-stage.
// ---------------------------------------------------------------------------
__global__ __launch_bounds__(128, 2) void flash_mma(
    const bf16* __restrict__ qh, const bf16* __restrict__ ql,
    const bf16* __restrict__ kh, const bf16* __restrict__ kl,
    const bf16* __restrict__ vh, const bf16* __restrict__ vl,
    bf16* __restrict__ oh, bf16* __restrict__ ol) {
    extern __shared__ char smem[];
    const uint32_t sb = su32(smem);
    const uint32_t oQh = 0, oQl = 16384, oKh = 32768, oKl = 49152,
                   oVh = 65536, oVl = 81920;
    const int tid = threadIdx.x, lane = tid & 31, warp = tid >> 5;
    const int bid = blockIdx.x;
    const int mt = 63 - (bid >> 2), b = bid & 3;        // heavy tiles first
    const int m0 = mt * 64, ntiles = mt + 1;
    const size_t boff = (size_t)b * TLEN * DDIM;
    const bf16 *Qh = qh + boff, *Ql = ql + boff, *Kh = kh + boff, *Kl = kl + boff,
               *Vh = vh + boff, *Vl = vl + boff;
    const int wm = warp * 16;
    const int gr = lane >> 2, j2 = (lane & 3) * 2;

    auto loadKV = [&](int n0) {
        for (int u = tid; u < 1024; u += 128) {
            int r = u >> 4, cc = u & 15;
            uint32_t sw = sw256(r, cc * 16);
            size_t src = (size_t)(n0 + r) * 128 + cc * 8;
            cp16(sb + oKh + sw, Kh + src);
            cp16(sb + oKl + sw, Kl + src);
            cp16(sb + oVh + sw, Vh + src);
            cp16(sb + oVl + sw, Vl + src);
        }
        CP_COMMIT();
    };

    // Q load + first KV tile
    for (int u = tid; u < 1024; u += 128) {
        int r = u >> 4, cc = u & 15;
        uint32_t sw = sw256(r, cc * 16);
        size_t src = (size_t)(m0 + r) * 128 + cc * 8;
        cp16(sb + oQh + sw, Qh + src);
        cp16(sb + oQl + sw, Ql + src);
    }
    loadKV(0);
    cp_wait<0>();
    __syncthreads();

    float o[16][4];
#pragma unroll
    for (int i = 0; i < 16; i++)
#pragma unroll
        for (int u = 0; u < 4; u++) o[i][u] = 0.f;
    float rm[2] = {-INFINITY, -INFINITY}, rl[2] = {0.f, 0.f};

    for (int nt = 0; nt < ntiles; nt++) {
        // ---- S = Q K^T (3-pass split) ----
        float s[8][4];
#pragma unroll
        for (int i = 0; i < 8; i++)
#pragma unroll
            for (int u = 0; u < 4; u++) s[i][u] = 0.f;
#pragma unroll
        for (int ks = 0; ks < 8; ks++) {
            uint32_t qa_h[4], qa_l[4];
            {
                int row = wm + (lane & 15);
                int cb = ks * 32 + ((lane >> 4) << 4);
                uint32_t sw = sw256(row, cb);
                LDSM4(qa_h, sb + oQh + sw);
                LDSM4(qa_l, sb + oQl + sw);
            }
#pragma unroll
            for (int pr = 0; pr < 4; pr++) {
                uint32_t kb_h[4], kb_l[4];
                int row = pr * 16 + ((lane >> 4) << 3) + (lane & 7);
                int cb = ks * 32 + (((lane >> 3) & 1) << 4);
                uint32_t sw = sw256(row, cb);
                LDSM4(kb_h, sb + oKh + sw);
                LDSM4(kb_l, sb + oKl + sw);
                MMA16816(s[pr*2],   qa_h, kb_h[0], kb_h[1]);
                MMA16816(s[pr*2],   qa_l, kb_h[0], kb_h[1]);
                MMA16816(s[pr*2],   qa_h, kb_l[0], kb_l[1]);
                MMA16816(s[pr*2+1], qa_h, kb_h[2], kb_h[3]);
                MMA16816(s[pr*2+1], qa_l, kb_h[2], kb_h[3]);
                MMA16816(s[pr*2+1], qa_h, kb_l[2], kb_l[3]);
            }
        }

        // ---- causal mask on diagonal tile (n0 == m0) ----
        if (nt == ntiles - 1) {
#pragma unroll
            for (int nt8 = 0; nt8 < 8; nt8++) {
#pragma unroll
                for (int c = 0; c < 4; c++) {
                    int col = nt8 * 8 + j2 + (c & 1);
                    int row = wm + gr + ((c >> 1) << 3);
                    if (col > row) s[nt8][c] = -1e30f;
                }
            }
        }

        // ---- online softmax (rows within warp quads) ----
        float mx0 = -INFINITY, mx1 = -INFINITY;
#pragma unroll
        for (int i = 0; i < 8; i++) {
            mx0 = fmaxf(mx0, fmaxf(s[i][0], s[i][1]));
            mx1 = fmaxf(mx1, fmaxf(s[i][2], s[i][3]));
        }
        mx0 = fmaxf(mx0, __shfl_xor_sync(0xffffffffu, mx0, 1));
        mx0 = fmaxf(mx0, __shfl_xor_sync(0xffffffffu, mx0, 2));
        mx1 = fmaxf(mx1, __shfl_xor_sync(0xffffffffu, mx1, 1));
        mx1 = fmaxf(mx1, __shfl_xor_sync(0xffffffffu, mx1, 2));
        float mn0 = fmaxf(rm[0], mx0), mn1 = fmaxf(rm[1], mx1);
        float sc0 = ex2(rm[0] - mn0), sc1 = ex2(rm[1] - mn1);
        float sum0 = 0.f, sum1 = 0.f;
#pragma unroll
        for (int i = 0; i < 8; i++) {
            s[i][0] = ex2(s[i][0] - mn0); sum0 += s[i][0];
            s[i][1] = ex2(s[i][1] - mn0); sum0 += s[i][1];
            s[i][2] = ex2(s[i][2] - mn1); sum1 += s[i][2];
            s[i][3] = ex2(s[i][3] - mn1); sum1 += s[i][3];
        }
        sum0 += __shfl_xor_sync(0xffffffffu, sum0, 1);
        sum0 += __shfl_xor_sync(0xffffffffu, sum0, 2);
        sum1 += __shfl_xor_sync(0xffffffffu, sum1, 1);
        sum1 += __shfl_xor_sync(0xffffffffu, sum1, 2);
        rl[0] = rl[0] * sc0 + sum0; rl[1] = rl[1] * sc1 + sum1;
        rm[0] = mn0; rm[1] = mn1;
#pragma unroll
        for (int i = 0; i < 16; i++) {
            o[i][0] *= sc0; o[i][1] *= sc0; o[i][2] *= sc1; o[i][3] *= sc1;
        }

        // ---- pack P to bf16 hi/lo in registers (A-fragment layout) ----
        uint32_t ph[8][2], pl[8][2];
#pragma unroll
        for (int i = 0; i < 8; i++) {
            uint32_t h0 = pk2(s[i][0], s[i][1]);
            uint32_t h1 = pk2(s[i][2], s[i][3]);
            ph[i][0] = h0; ph[i][1] = h1;
            pl[i][0] = pk2(s[i][0] - lo_f(h0), s[i][1] - hi_f(h0));
            pl[i][1] = pk2(s[i][2] - lo_f(h1), s[i][3] - hi_f(h1));
        }

        // ---- O += P V (3-pass split) ----
#pragma unroll
        for (int kk = 0; kk < 4; kk++) {
            uint32_t pa_h[4] = {ph[kk*2][0], ph[kk*2][1], ph[kk*2+1][0], ph[kk*2+1][1]};
            uint32_t pa_l[4] = {pl[kk*2][0], pl[kk*2][1], pl[kk*2+1][0], pl[kk*2+1][1]};
#pragma unroll
            for (int dt = 0; dt < 8; dt++) {
                uint32_t vf_h[4], vf_l[4];
                int row = kk * 16 + (lane & 7) + (((lane >> 3) & 1) << 3);
                int cb = dt * 32 + ((lane >> 4) << 4);
                uint32_t sw = sw256(row, cb);
                LDSM4T(vf_h, sb + oVh + sw);
                LDSM4T(vf_l, sb + oVl + sw);
                MMA16816(o[dt*2],   pa_h, vf_h[0], vf_h[1]);
                MMA16816(o[dt*2],   pa_l, vf_h[0], vf_h[1]);
                MMA16816(o[dt*2],   pa_h, vf_l[0], vf_l[1]);
                MMA16816(o[dt*2+1], pa_h, vf_h[2], vf_h[3]);
                MMA16816(o[dt*2+1], pa_l, vf_h[2], vf_h[3]);
                MMA16816(o[dt*2+1], pa_h, vf_l[2], vf_l[3]);
            }
        }

        __syncthreads();
        if (nt + 1 < ntiles) {
            loadKV((nt + 1) * 64);
            cp_wait<0>();
        }
        __syncthreads();
    }

    // ---- epilogue: normalize, split to bf16 hi/lo ----
    float inv0 = 1.f / rl[0], inv1 = 1.f / rl[1];
    size_t row0 = (size_t)b * TLEN + m0 + wm + gr;
#pragma unroll
    for (int dt = 0; dt < 16; dt++) {
        int col = dt * 8 + j2;
        float v0 = o[dt][0] * inv0, v1 = o[dt][1] * inv0;
        float v2 = o[dt][2] * inv1, v3 = o[dt][3] * inv1;
        uint32_t h0 = pk2(v0, v1), h1 = pk2(v2, v3);
        *(uint32_t*)(oh + row0 * 128 + col) = h0;
        *(uint32_t*)(ol + row0 * 128 + col) = pk2(v0 - lo_f(h0), v1 - hi_f(h0));
        *(uint32_t*)(oh + (row0 + 8) * 128 + col) = h1;
        *(uint32_t*)(ol + (row0 + 8) * 128 + col) = pk2(v2 - lo_f(h1), v3 - hi_f(h1));
    }
}

// ---------------------------------------------------------------------------
extern "C" void kernel_launch(void* const* d_in, const int* in_sizes, int n_in,
                              void* d_out, int out_size) {
    const float* x  = (const float*)d_in[0];
    const float* Wk = (const float*)d_in[1];
    const float* Wq = (const float*)d_in[2];
    const float* Wv = (const float*)d_in[3];
    const float* Wp = (const float*)d_in[4];
    float* out = (float*)d_out;

    bf16 *xh, *xl, *wth, *wtl, *wpth, *wptl;
    bf16 *qh, *ql, *kh, *kl, *vh, *vl, *oh, *ol;
    cudaGetSymbolAddress((void**)&xh, g_xh);   cudaGetSymbolAddress((void**)&xl, g_xl);
    cudaGetSymbolAddress((void**)&wth, g_wth); cudaGetSymbolAddress((void**)&wtl, g_wtl);
    cudaGetSymbolAddress((void**)&wpth, g_wpth); cudaGetSymbolAddress((void**)&wptl, g_wptl);
    cudaGetSymbolAddress((void**)&qh, g_qh);   cudaGetSymbolAddress((void**)&ql, g_ql);
    cudaGetSymbolAddress((void**)&kh, g_kh);   cudaGetSymbolAddress((void**)&kl, g_kl);
    cudaGetSymbolAddress((void**)&vh, g_vh);   cudaGetSymbolAddress((void**)&vl, g_vl);
    cudaGetSymbolAddress((void**)&oh, g_oh);   cudaGetSymbolAddress((void**)&ol, g_ol);

    const int mm_smem = 131072;   // 2 stages x 64KB
    const int fa_smem = 98304;    // Q(32K) + K(32K) + V(32K)
    cudaFuncSetAttribute(mm_bf16<1>, cudaFuncAttributeMaxDynamicSharedMemorySize, mm_smem);
    cudaFuncSetAttribute(mm_bf16<0>, cudaFuncAttributeMaxDynamicSharedMemorySize, mm_smem);
    cudaFuncSetAttribute(flash_mma, cudaFuncAttributeMaxDynamicSharedMemorySize, fa_smem);

    split_f32<<<MTOT * EDIM / 4 / 256, 256>>>(x, xh, xl, MTOT * EDIM / 4);
    convert_w<<<(3 * DDIM * EDIM + 255) / 256, 256>>>(Wq, Wk, Wv, Wp, wth, wtl, wpth, wptl);

    mm_bf16<1><<<MTOT / 128, 256, mm_smem>>>(xh, xl, wth, wtl,
                                             nullptr, qh, ql, QSCALE, EDIM);
    mm_bf16<1><<<MTOT / 128, 256, mm_smem>>>(xh, xl, wth + 1 * DDIM * EDIM, wtl + 1 * DDIM * EDIM,
                                             nullptr, kh, kl, 1.f, EDIM);
    mm_bf16<1><<<MTOT / 128, 256, mm_smem>>>(xh, xl, wth + 2 * DDIM * EDIM, wtl + 2 * DDIM * EDIM,
                                             nullptr, vh, vl, 1.f, EDIM);

    flash_mma<<<4 * 64, 128, fa_smem>>>(qh, ql, kh, kl, vh, vl, oh, ol);

    mm_bf16<0><<<MTOT / 128, 256, mm_smem>>>(oh, ol, wpth, wptl,
                                             out, nullptr, nullptr, 1.f, DDIM);
}